// round 16
// baseline (speedup 1.0000x reference)
#include <cuda_runtime.h>
#include <cuda_fp16.h>
#include <math.h>
#include <stdint.h>

#define BATCH   2
#define SEQ     2048
#define DMODEL  1024
#define NHEADS  16
#define DKV     64
#define INNER   1024
#define NTOK    (BATCH*SEQ)          // 4096
#define RBR     (2*SEQ-1)            // 4095

// -------- scratch (device globals: no allocation allowed) --------
__device__ __half g_Xhi[NTOK*DMODEL],  g_Xlo[NTOK*DMODEL];
__device__ __half g_Whi[4*DMODEL*INNER], g_Wlo[4*DMODEL*INNER];
__device__ __half g_Qhi[NTOK*INNER],  g_Qlo[NTOK*INNER];
__device__ __half g_Khi[NTOK*INNER];
__device__ __half g_Vthi[NTOK*INNER], g_Vtlo[NTOK*INNER];   // transposed [n][token]
__device__ __half g_Chi[NTOK*INNER],  g_Clo[NTOK*INNER];
__device__ float  g_RB[RBR*NHEADS];

// ============================================================
// helpers
// ============================================================
__device__ __forceinline__ uint32_t smem_u32(const void* p) {
    uint32_t a;
    asm("{ .reg .u64 t; cvta.to.shared.u64 t, %1; cvt.u32.u64 %0, t; }" : "=r"(a) : "l"(p));
    return a;
}
__device__ __forceinline__ void cp_async16(uint32_t dst, const void* src) {
    asm volatile("cp.async.cg.shared.global [%0], [%1], 16;\n" :: "r"(dst), "l"(src) : "memory");
}
#define CP_ASYNC_COMMIT() asm volatile("cp.async.commit_group;\n" ::: "memory")
#define CP_ASYNC_WAIT(n)  asm volatile("cp.async.wait_group %0;\n" :: "n"(n) : "memory")

__device__ __forceinline__ void ldmatrix_x4(uint32_t* r, uint32_t addr) {
    asm volatile("ldmatrix.sync.aligned.m8n8.x4.shared.b16 {%0,%1,%2,%3}, [%4];"
                 : "=r"(r[0]), "=r"(r[1]), "=r"(r[2]), "=r"(r[3]) : "r"(addr));
}
__device__ __forceinline__ void mma_f16(float* d, const uint32_t* a, const uint32_t* b) {
    asm volatile(
        "mma.sync.aligned.m16n8k16.row.col.f32.f16.f16.f32 "
        "{%0,%1,%2,%3}, {%4,%5,%6,%7}, {%8,%9}, {%0,%1,%2,%3};"
        : "+f"(d[0]), "+f"(d[1]), "+f"(d[2]), "+f"(d[3])
        : "r"(a[0]), "r"(a[1]), "r"(a[2]), "r"(a[3]), "r"(b[0]), "r"(b[1]));
}
__device__ __forceinline__ void split2(float f0, float f1, uint32_t& hi, uint32_t& lo) {
    __half h0 = __float2half_rn(f0), h1 = __float2half_rn(f1);
    __half l0 = __float2half_rn(f0 - __half2float(h0));
    __half l1 = __float2half_rn(f1 - __half2float(h1));
    hi = (uint32_t)__half_as_ushort(h0) | ((uint32_t)__half_as_ushort(h1) << 16);
    lo = (uint32_t)__half_as_ushort(l0) | ((uint32_t)__half_as_ushort(l1) << 16);
}
__device__ __forceinline__ uint32_t pack_half2(float f0, float f1) {
    __half2 h = __floats2half2_rn(f0, f1);
    return *(uint32_t*)&h;
}

// =============================================================
// Fused pre-processing: one launch.
//  blocks [0, 4096)      : X split (float4 x 1024 per block)
//  blocks [4096, 8192)   : weight transpose+split, remapped to
//                          (tx 0..31, ty 0..31, z 0..3)
//  block  8192           : bias table (loops all entries)
// Per-element math identical to the three separate kernels.
// =============================================================
#define PRE_SPLIT_BLOCKS 4096
#define PRE_TRANS_BLOCKS 4096
#define PRE_TOTAL (PRE_SPLIT_BLOCKS + PRE_TRANS_BLOCKS + 1)

__global__ __launch_bounds__(256)
void preproc_kernel(const float* __restrict__ X,
                    const float* __restrict__ w0, const float* __restrict__ w1,
                    const float* __restrict__ w2, const float* __restrict__ w3,
                    const float* __restrict__ table,
                    __half* __restrict__ Xhi, __half* __restrict__ Xlo,
                    __half* __restrict__ Whi_base, __half* __restrict__ Wlo_base)
{
    const int blk = blockIdx.x;

    if (blk < PRE_SPLIT_BLOCKS) {
        // ---- X split ----
        int i = blk * 256 + threadIdx.x;     // float4 index, n4 = 1048576 exactly
        float4 v = ((const float4*)X)[i];
        uint32_t h0, l0, h1, l1;
        split2(v.x, v.y, h0, l0);
        split2(v.z, v.w, h1, l1);
        *(uint2*)(Xhi + 4l * i) = make_uint2(h0, h1);
        *(uint2*)(Xlo + 4l * i) = make_uint2(l0, l1);
        return;
    }

    if (blk < PRE_SPLIT_BLOCKS + PRE_TRANS_BLOCKS) {
        // ---- weight transpose + split ----
        __shared__ float tile[32][33];
        int id = blk - PRE_SPLIT_BLOCKS;     // 0..4095
        int z  = id >> 10;                   // weight index 0..3
        int bidx = id & 1023;
        int bxx = bidx & 31, byy = bidx >> 5;

        const float* in = (z == 0) ? w0 : (z == 1) ? w1 : (z == 2) ? w2 : w3;
        __half* hi = Whi_base + (long)z * DMODEL * INNER;
        __half* lo = Wlo_base + (long)z * DMODEL * INNER;

        int tx = threadIdx.x & 31, ty = threadIdx.x >> 5;   // ty 0..7
        int bx = bxx * 32, by = byy * 32;
        int x = bx + tx;
        #pragma unroll
        for (int i = 0; i < 32; i += 8)
            tile[ty + i][tx] = in[(by + ty + i) * DMODEL + x];
        __syncthreads();
        x = by + tx;
        #pragma unroll
        for (int i = 0; i < 32; i += 8) {
            float v = tile[tx][ty + i];
            __half h = __float2half_rn(v);
            __half l = __float2half_rn(v - __half2float(h));
            long idx = (long)(bx + ty + i) * DMODEL + x;
            hi[idx] = h;
            lo[idx] = l;
        }
        return;
    }

    // ---- bias table (single block, loops) ----
    for (int idx = threadIdx.x; idx < RBR * NHEADS; idx += 256) {
        int rel = idx / NHEADS - (SEQ - 1);
        int h   = idx % NHEADS;
        int bucket = (rel > 0) ? 16 : 0;
        int rp = rel < 0 ? -rel : rel;
        int v;
        if (rp < 8) {
            v = rp;
        } else {
            float f = logf((float)rp * 0.125f) / 2.772588722239781f * 8.0f;
            v = 8 + (int)f;
            if (v > 15) v = 15;
        }
        g_RB[idx] = table[(bucket + v) * NHEADS + h];
    }
}

// =============================================================
// GEMM plumbing (R9/R13 config): 4-stage cp.async ring, per-chunk
// commit, wait(2). 128 thr / 4 warps, warp tile 64x64.
// =============================================================
#define HPAD 24
#define TILE_B 6144
#define STAGE_B 24576
#define NSTAGE 4
#define HGEMM_SMEM (NSTAGE * STAGE_B) // 98304
#define NITER (DMODEL / 16)           // 64

// =============================================================
// Fused QKV projection. Grid (24, 32), 128 threads.
// LPT order: bx 0-7 -> V, 8-15 -> K, 16-23 -> Q. K writes hi only.
// =============================================================
__global__ __launch_bounds__(128)
void qkv_kernel(const __half* __restrict__ Xhi, const __half* __restrict__ Xlo,
                const __half* __restrict__ Whi_base, const __half* __restrict__ Wlo_base,
                __half* __restrict__ Qhi, __half* __restrict__ Qlo,
                __half* __restrict__ Khi,
                __half* __restrict__ Vthi, __half* __restrict__ Vtlo)
{
    extern __shared__ __half hsm[];
    const int mat  = 2 - (blockIdx.x >> 3);   // bx 0-7: V(2), 8-15: K(1), 16-23: Q(0)
    const bool isV = (mat == 2);
    const __half* Bhi = Whi_base + (long)mat * DMODEL * INNER;
    const __half* Blo = Wlo_base + (long)mat * DMODEL * INNER;

    const int tid  = threadIdx.x;
    const int wid  = tid >> 5;
    const int lane = tid & 31;
    const int wr   = wid & 1;
    const int wc   = wid >> 1;
    const long bm  = blockIdx.y * 128;
    const long bn  = (blockIdx.x & 7) * 128;
    const uint32_t s0 = smem_u32(hsm);

    float acc[4][8][4];
    #pragma unroll
    for (int i = 0; i < 4; i++)
        #pragma unroll
        for (int j = 0; j < 8; j++)
            #pragma unroll
            for (int k = 0; k < 4; k++) acc[i][j][k] = 0.0f;

    auto load_tiles = [&](int it, int stage) {
        int k0 = it * 16;
        uint32_t sbase = s0 + stage * STAGE_B;
        #pragma unroll
        for (int i = 0; i < 6; i++) {
            int id  = tid + i * 128;
            int sel = id >> 8;
            int wi  = id & 255;
            int row = wi >> 1, c = wi & 1;
            uint32_t off = sel * TILE_B + row * (HPAD * 2) + c * 16;
            long ao = (bm + row) * (long)DMODEL + k0 + c * 8;
            long bo = (bn + row) * (long)DMODEL + k0 + c * 8;
            const __half* src = (sel == 0) ? Xhi + ao : (sel == 1) ? Xlo + ao : Bhi + bo;
            cp_async16(sbase + off, src);
        }
        if (isV) {
            #pragma unroll
            for (int i = 0; i < 2; i++) {
                int wi  = tid + i * 128;
                int row = wi >> 1, c = wi & 1;
                uint32_t off = 3 * TILE_B + row * (HPAD * 2) + c * 16;
                cp_async16(sbase + off, Blo + (bn + row) * (long)DMODEL + k0 + c * 8);
            }
        }
        CP_ASYNC_COMMIT();
    };

    const int lrow  = lane & 15;
    const int lcolA = (lane >= 16) ? 16 : 0;
    const int brow  = (lane & 7) + ((lane & 16) ? 8 : 0);
    const int bcol  = (lane & 8) ? 16 : 0;

    load_tiles(0, 0);
    load_tiles(1, 1);
    load_tiles(2, 2);

    for (int it = 0; it < NITER; it++) {
        const int buf = it & 3;
        CP_ASYNC_WAIT(2);
        __syncthreads();
        if (it + 3 < NITER) load_tiles(it + 3, (it + 3) & 3);
        else                CP_ASYNC_COMMIT();

        const uint32_t ah  = s0 + buf * STAGE_B;
        const uint32_t al  = ah + TILE_B;
        const uint32_t bhB = ah + 2 * TILE_B;
        const uint32_t blB = ah + 3 * TILE_B;

        uint32_t afh[4][4], afl[4][4];
        #pragma unroll
        for (int mt = 0; mt < 4; mt++) {
            int m = wr * 64 + mt * 16 + lrow;
            ldmatrix_x4(afh[mt], ah + m * (HPAD * 2) + lcolA);
            ldmatrix_x4(afl[mt], al + m * (HPAD * 2) + lcolA);
        }
        uint32_t bfh[4][4], bfl[4][4];
        #pragma unroll
        for (int p = 0; p < 4; p++) {
            int n = wc * 64 + p * 16 + brow;
            ldmatrix_x4(bfh[p], bhB + n * (HPAD * 2) + bcol);
            if (isV) ldmatrix_x4(bfl[p], blB + n * (HPAD * 2) + bcol);
        }
        if (isV) {
            #pragma unroll
            for (int mt = 0; mt < 4; mt++)
                #pragma unroll
                for (int p = 0; p < 4; p++)
                    #pragma unroll
                    for (int sub = 0; sub < 2; sub++) {
                        float* a = acc[mt][2 * p + sub];
                        mma_f16(a, afh[mt], &bfh[p][sub * 2]);
                        mma_f16(a, afh[mt], &bfl[p][sub * 2]);
                        mma_f16(a, afl[mt], &bfh[p][sub * 2]);
                    }
        } else {
            #pragma unroll
            for (int mt = 0; mt < 4; mt++)
                #pragma unroll
                for (int p = 0; p < 4; p++)
                    #pragma unroll
                    for (int sub = 0; sub < 2; sub++) {
                        float* a = acc[mt][2 * p + sub];
                        mma_f16(a, afh[mt], &bfh[p][sub * 2]);
                        mma_f16(a, afl[mt], &bfh[p][sub * 2]);
                    }
        }
    }

    // epilogue
    __half* Chi = (mat == 0) ? Qhi : (mat == 1) ? Khi : Vthi;
    __half* Clo = (mat == 0) ? Qlo : Vtlo;      // only used for Q and V
    #pragma unroll
    for (int mt = 0; mt < 4; mt++) {
        long m0 = bm + wr * 64 + mt * 16 + (lane >> 2);
        #pragma unroll
        for (int nt = 0; nt < 8; nt++) {
            long n0 = bn + wc * 64 + nt * 8 + (lane & 3) * 2;
            float* a = acc[mt][nt];
            if (!isV) {
                uint32_t h, l;
                split2(a[0], a[1], h, l);
                *(uint32_t*)(Chi + m0 * INNER + n0) = h;
                if (mat == 0) *(uint32_t*)(Clo + m0 * INNER + n0) = l;
                split2(a[2], a[3], h, l);
                *(uint32_t*)(Chi + (m0 + 8) * INNER + n0) = h;
                if (mat == 0) *(uint32_t*)(Clo + (m0 + 8) * INNER + n0) = l;
            } else {
                #pragma unroll
                for (int e = 0; e < 4; e++) {
                    long m = m0 + ((e >= 2) ? 8 : 0);
                    long n = n0 + (e & 1);
                    __half h = __float2half_rn(a[e]);
                    __half l = __float2half_rn(a[e] - __half2float(h));
                    Chi[n * NTOK + m] = h;
                    Clo[n * NTOK + m] = l;
                }
            }
        }
    }
}

// =============================================================
// O-projection GEMM (3-MMA, float out) — R9/R13 config.
// =============================================================
__global__ __launch_bounds__(128)
void oproj_kernel(const __half* __restrict__ Ahi, const __half* __restrict__ Alo,
                  const __half* __restrict__ Bhi, const __half* __restrict__ Blo,
                  float* __restrict__ Cf)
{
    extern __shared__ __half hsm[];
    const int tid  = threadIdx.x;
    const int wid  = tid >> 5;
    const int lane = tid & 31;
    const int wr   = wid & 1;
    const int wc   = wid >> 1;
    const long bm  = blockIdx.y * 128;
    const long bn  = blockIdx.x * 128;
    const uint32_t s0 = smem_u32(hsm);

    float acc[4][8][4];
    #pragma unroll
    for (int i = 0; i < 4; i++)
        #pragma unroll
        for (int j = 0; j < 8; j++)
            #pragma unroll
            for (int k = 0; k < 4; k++) acc[i][j][k] = 0.0f;

    auto load_tiles = [&](int it, int stage) {
        int k0 = it * 16;
        uint32_t sbase = s0 + stage * STAGE_B;
        #pragma unroll
        for (int i = 0; i < 8; i++) {
            int id  = tid + i * 128;          // 0..1023
            int sel = id >> 8;                // 0 Ahi, 1 Alo, 2 Bhi, 3 Blo
            int wi  = id & 255;
            int row = wi >> 1, c = wi & 1;
            uint32_t off = sel * TILE_B + row * (HPAD * 2) + c * 16;
            long ao = (bm + row) * (long)DMODEL + k0 + c * 8;
            long bo = (bn + row) * (long)DMODEL + k0 + c * 8;
            const __half* src = (sel == 0) ? Ahi + ao : (sel == 1) ? Alo + ao
                              : (sel == 2) ? Bhi + bo : Blo + bo;
            cp_async16(sbase + off, src);
        }
        CP_ASYNC_COMMIT();
    };

    const int lrow  = lane & 15;
    const int lcolA = (lane >= 16) ? 16 : 0;
    const int brow  = (lane & 7) + ((lane & 16) ? 8 : 0);
    const int bcol  = (lane & 8) ? 16 : 0;

    load_tiles(0, 0);
    load_tiles(1, 1);
    load_tiles(2, 2);

    for (int it = 0; it < NITER; it++) {
        const int buf = it & 3;
        CP_ASYNC_WAIT(2);
        __syncthreads();
        if (it + 3 < NITER) load_tiles(it + 3, (it + 3) & 3);
        else                CP_ASYNC_COMMIT();

        const uint32_t ah  = s0 + buf * STAGE_B;
        const uint32_t al  = ah + TILE_B;
        const uint32_t bhB = ah + 2 * TILE_B;
        const uint32_t blB = ah + 3 * TILE_B;

        uint32_t afh[4][4], afl[4][4];
        #pragma unroll
        for (int mt = 0; mt < 4; mt++) {
            int m = wr * 64 + mt * 16 + lrow;
            ldmatrix_x4(afh[mt], ah + m * (HPAD * 2) + lcolA);
            ldmatrix_x4(afl[mt], al + m * (HPAD * 2) + lcolA);
        }
        uint32_t bfh[4][4], bfl[4][4];
        #pragma unroll
        for (int p = 0; p < 4; p++) {
            int n = wc * 64 + p * 16 + brow;
            ldmatrix_x4(bfh[p], bhB + n * (HPAD * 2) + bcol);
            ldmatrix_x4(bfl[p], blB + n * (HPAD * 2) + bcol);
        }
        #pragma unroll
        for (int mt = 0; mt < 4; mt++)
            #pragma unroll
            for (int p = 0; p < 4; p++)
                #pragma unroll
                for (int sub = 0; sub < 2; sub++) {
                    float* a = acc[mt][2 * p + sub];
                    mma_f16(a, afh[mt], &bfh[p][sub * 2]);
                    mma_f16(a, afh[mt], &bfl[p][sub * 2]);
                    mma_f16(a, afl[mt], &bfh[p][sub * 2]);
                }
    }

    #pragma unroll
    for (int mt = 0; mt < 4; mt++) {
        long m0 = bm + wr * 64 + mt * 16 + (lane >> 2);
        #pragma unroll
        for (int nt = 0; nt < 8; nt++) {
            long n0 = bn + wc * 64 + nt * 8 + (lane & 3) * 2;
            float* a = acc[mt][nt];
            *(float2*)(Cf + m0 * INNER + n0)       = make_float2(a[0], a[1]);
            *(float2*)(Cf + (m0 + 8) * INNER + n0) = make_float2(a[2], a[3]);
        }
    }
}

// =============================================================
// fp16-split flash attention: single barrier per k-tile, bias
// slice double-buffered and prefetched one tile ahead.
// =============================================================
#define KSTAGE 27648
#define QOFF   27648
#define RBOFF  (QOFF + 36864)
#define ATT_SMEM (RBOFF + 2*192*4)
#define KROWB 144

__global__ __launch_bounds__(128, 2)
void attn_kernel(const __half* __restrict__ Qhi, const __half* __restrict__ Qlo,
                 const __half* __restrict__ Khi,
                 const __half* __restrict__ Vthi, const __half* __restrict__ Vtlo,
                 __half* __restrict__ Chi, __half* __restrict__ Clo)
{
    extern __shared__ char smraw[];
    float* rbs = (float*)(smraw + RBOFF);   // two buffers of 192 floats
    const int tid  = threadIdx.x;
    const int w    = tid >> 5;
    const int lane = tid & 31;
    const int bh   = blockIdx.y;
    const int b    = bh >> 4;
    const int h    = bh & 15;
    const int q0   = blockIdx.x * 128;
    const uint32_t sb = smem_u32(smraw);
    const int grow = lane >> 2;
    const int gc   = (lane & 3) * 2;

    auto load_kv = [&](int t, int stage) {
        int k0 = t * 64;
        uint32_t sbase = sb + stage * KSTAGE;
        #pragma unroll
        for (int i = 0; i < 12; i++) {
            int id  = tid + i * 128;
            int sel = id >> 9;
            int wi  = id & 511;
            int row = wi >> 3, c = wi & 7;
            uint32_t dst = sbase + sel * 9216 + row * KROWB + c * 16;
            const __half* src;
            if (sel == 0) {
                src = Khi + (long)(b * SEQ + k0 + row) * INNER + h * DKV + c * 8;
            } else {
                const __half* base = (sel == 2) ? Vtlo : Vthi;
                src = base + (long)(h * DKV + row) * NTOK + b * SEQ + k0 + c * 8;
            }
            cp_async16(dst, src);
        }
        CP_ASYNC_COMMIT();
    };
    auto load_rbs = [&](int t) {
        float* dst = rbs + (t & 1) * 192;
        for (int i = tid; i < 191; i += 128)
            dst[i] = g_RB[(t * 64 - q0 + i - 127 + SEQ - 1) * NHEADS + h];
    };

    // ---- prologue: Q + kv0, rbs buffer 0 ----
    #pragma unroll
    for (int i = 0; i < 16; i++) {
        int id  = tid + i * 128;
        int sel = id >> 10;
        int wi  = id & 1023;
        int row = wi >> 3, c = wi & 7;
        uint32_t dst = sb + QOFF + sel * 18432 + row * KROWB + c * 16;
        const __half* src = (sel ? Qlo : Qhi) +
                            (long)(b * SEQ + q0 + row) * INNER + h * DKV + c * 8;
        cp_async16(dst, src);
    }
    load_kv(0, 0);
    load_rbs(0);
    CP_ASYNC_WAIT(0);
    __syncthreads();

    uint32_t qh[2][4][4], ql[2][4][4];
    {
        uint32_t qbh = sb + QOFF;
        uint32_t qbl = qbh + 18432;
        int cofs = (lane >= 16) ? 16 : 0;
        #pragma unroll
        for (int hf = 0; hf < 2; hf++) {
            int r = w * 32 + hf * 16 + (lane & 15);
            #pragma unroll
            for (int ks = 0; ks < 4; ks++) {
                ldmatrix_x4(qh[hf][ks], qbh + r * KROWB + ks * 32 + cofs);
                ldmatrix_x4(ql[hf][ks], qbl + r * KROWB + ks * 32 + cofs);
            }
        }
    }

    float m[2][2], l[2][2];
    float o[2][8][4];
    #pragma unroll
    for (int hf = 0; hf < 2; hf++) {
        m[hf][0] = m[hf][1] = -3.0e38f;
        l[hf][0] = l[hf][1] = 0.0f;
        #pragma unroll
        for (int nt = 0; nt < 8; nt++)
            #pragma unroll
            for (int e = 0; e < 4; e++) o[hf][nt][e] = 0.0f;
    }

    for (int t = 0; t < SEQ / 64; t++) {
        __syncthreads();   // one barrier per tile
        if (t + 1 < SEQ / 64) {
            load_kv(t + 1, (t + 1) & 1);
            load_rbs(t + 1);            // prefetch bias for next tile
            CP_ASYNC_WAIT(1);           // kv_t complete
        } else {
            CP_ASYNC_WAIT(0);
        }

        const char* kp = smraw + (t & 1) * KSTAGE;
        const char* vh = kp + 9216;
        const char* vl = kp + 18432;
        const float* rb = rbs + (t & 1) * 192;

        float s[2][8][4];
        #pragma unroll
        for (int hf = 0; hf < 2; hf++)
            #pragma unroll
            for (int nt = 0; nt < 8; nt++)
                #pragma unroll
                for (int e = 0; e < 4; e++) s[hf][nt][e] = 0.0f;

        #pragma unroll
        for (int ks = 0; ks < 4; ks++) {
            #pragma unroll
            for (int nt = 0; nt < 8; nt++) {
                uint32_t off = (nt * 8 + grow) * KROWB + ks * 32 + gc * 2;
                uint32_t bh_[2];
                bh_[0] = *(const uint32_t*)(kp + off);
                bh_[1] = *(const uint32_t*)(kp + off + 16);
                mma_f16(s[0][nt], qh[0][ks], bh_);
                mma_f16(s[0][nt], ql[0][ks], bh_);
                mma_f16(s[1][nt], qh[1][ks], bh_);
                mma_f16(s[1][nt], ql[1][ks], bh_);
            }
        }

        #pragma unroll
        for (int hf = 0; hf < 2; hf++) {
            const int rb0 = 127 - (w * 32 + hf * 16 + grow);
            #pragma unroll
            for (int nt = 0; nt < 8; nt++) {
                int cb = nt * 8 + gc;
                s[hf][nt][0] += rb[cb + rb0];
                s[hf][nt][1] += rb[cb + 1 + rb0];
                s[hf][nt][2] += rb[cb + rb0 - 8];
                s[hf][nt][3] += rb[cb + 1 + rb0 - 8];
            }
            float tm0 = -3.0e38f, tm1 = -3.0e38f;
            #pragma unroll
            for (int nt = 0; nt < 8; nt++) {
                tm0 = fmaxf(tm0, fmaxf(s[hf][nt][0], s[hf][nt][1]));
                tm1 = fmaxf(tm1, fmaxf(s[hf][nt][2], s[hf][nt][3]));
            }
            tm0 = fmaxf(tm0, __shfl_xor_sync(0xffffffffu, tm0, 1));
            tm0 = fmaxf(tm0, __shfl_xor_sync(0xffffffffu, tm0, 2));
            tm1 = fmaxf(tm1, __shfl_xor_sync(0xffffffffu, tm1, 1));
            tm1 = fmaxf(tm1, __shfl_xor_sync(0xffffffffu, tm1, 2));
            float nm0 = fmaxf(m[hf][0], tm0), nm1 = fmaxf(m[hf][1], tm1);
            float sc0 = __expf(m[hf][0] - nm0), sc1 = __expf(m[hf][1] - nm1);
            float ls0 = 0.0f, ls1 = 0.0f;
            #pragma unroll
            for (int nt = 0; nt < 8; nt++) {
                s[hf][nt][0] = __expf(s[hf][nt][0] - nm0); ls0 += s[hf][nt][0];
                s[hf][nt][1] = __expf(s[hf][nt][1] - nm0); ls0 += s[hf][nt][1];
                s[hf][nt][2] = __expf(s[hf][nt][2] - nm1); ls1 += s[hf][nt][2];
                s[hf][nt][3] = __expf(s[hf][nt][3] - nm1); ls1 += s[hf][nt][3];
            }
            ls0 += __shfl_xor_sync(0xffffffffu, ls0, 1);
            ls0 += __shfl_xor_sync(0xffffffffu, ls0, 2);
            ls1 += __shfl_xor_sync(0xffffffffu, ls1, 1);
            ls1 += __shfl_xor_sync(0xffffffffu, ls1, 2);
            l[hf][0] = l[hf][0] * sc0 + ls0;
            l[hf][1] = l[hf][1] * sc1 + ls1;
            m[hf][0] = nm0;  m[hf][1] = nm1;
            #pragma unroll
            for (int nt = 0; nt < 8; nt++) {
                o[hf][nt][0] *= sc0; o[hf][nt][1] *= sc0;
                o[hf][nt][2] *= sc1; o[hf][nt][3] *= sc1;
            }
        }

        #pragma unroll
        for (int ks = 0; ks < 4; ks++) {
            uint32_t ph[2][4];
            #pragma unroll
            for (int hf = 0; hf < 2; hf++) {
                ph[hf][0] = pack_half2(s[hf][2*ks][0],   s[hf][2*ks][1]);
                ph[hf][1] = pack_half2(s[hf][2*ks][2],   s[hf][2*ks][3]);
                ph[hf][2] = pack_half2(s[hf][2*ks+1][0], s[hf][2*ks+1][1]);
                ph[hf][3] = pack_half2(s[hf][2*ks+1][2], s[hf][2*ks+1][3]);
            }
            #pragma unroll
            for (int nt = 0; nt < 8; nt++) {
                uint32_t off = (nt * 8 + grow) * KROWB + ks * 32 + gc * 2;
                uint32_t vh_[2], vl_[2];
                vh_[0] = *(const uint32_t*)(vh + off);
                vh_[1] = *(const uint32_t*)(vh + off + 16);
                vl_[0] = *(const uint32_t*)(vl + off);
                vl_[1] = *(const uint32_t*)(vl + off + 16);
                mma_f16(o[0][nt], ph[0], vh_);
                mma_f16(o[0][nt], ph[0], vl_);
                mma_f16(o[1][nt], ph[1], vh_);
                mma_f16(o[1][nt], ph[1], vl_);
            }
        }
    }

    #pragma unroll
    for (int hf = 0; hf < 2; hf++) {
        float i0 = 1.0f / l[hf][0], i1 = 1.0f / l[hf][1];
        long tok0 = (long)b * SEQ + q0 + w * 32 + hf * 16 + grow;
        #pragma unroll
        for (int nt = 0; nt < 8; nt++) {
            long col = h * DKV + nt * 8 + gc;
            uint32_t hh, ll;
            split2(o[hf][nt][0] * i0, o[hf][nt][1] * i0, hh, ll);
            *(uint32_t*)(Chi + tok0 * INNER + col) = hh;
            *(uint32_t*)(Clo + tok0 * INNER + col) = ll;
            split2(o[hf][nt][2] * i1, o[hf][nt][3] * i1, hh, ll);
            *(uint32_t*)(Chi + (tok0 + 8) * INNER + col) = hh;
            *(uint32_t*)(Clo + (tok0 + 8) * INNER + col) = ll;
        }
    }
}

// =============================================================
// Host launcher
// =============================================================
extern "C" void kernel_launch(void* const* d_in, const int* in_sizes, int n_in,
                              void* d_out, int out_size)
{
    const float* X   = (const float*)d_in[0];
    const float* wq  = (const float*)d_in[1];
    const float* wk  = (const float*)d_in[2];
    const float* wv  = (const float*)d_in[3];
    const float* wo  = (const float*)d_in[4];
    const float* rbt = (const float*)d_in[5];
    float* out = (float*)d_out;

    __half *Xhi, *Xlo, *Whi, *Wlo, *Qhi, *Qlo, *Khi, *Vthi, *Vtlo, *Chi, *Clo;
    cudaGetSymbolAddress((void**)&Xhi,  g_Xhi);   cudaGetSymbolAddress((void**)&Xlo,  g_Xlo);
    cudaGetSymbolAddress((void**)&Whi,  g_Whi);   cudaGetSymbolAddress((void**)&Wlo,  g_Wlo);
    cudaGetSymbolAddress((void**)&Qhi,  g_Qhi);   cudaGetSymbolAddress((void**)&Qlo,  g_Qlo);
    cudaGetSymbolAddress((void**)&Khi,  g_Khi);
    cudaGetSymbolAddress((void**)&Vthi, g_Vthi);  cudaGetSymbolAddress((void**)&Vtlo, g_Vtlo);
    cudaGetSymbolAddress((void**)&Chi,  g_Chi);   cudaGetSymbolAddress((void**)&Clo,  g_Clo);

    const long WOFF = (long)DMODEL * INNER;

    // fused preprocessing (one launch: split + 4 transposes + bias table)
    preproc_kernel<<<PRE_TOTAL, 256>>>(X, wq, wk, wv, wo, rbt, Xhi, Xlo, Whi, Wlo);

    // fused QKV projections (R13 config: R9-shape loop, LPT order, K hi-only)
    cudaFuncSetAttribute(qkv_kernel, cudaFuncAttributeMaxDynamicSharedMemorySize, HGEMM_SMEM);
    qkv_kernel<<<dim3(24, 32), 128, HGEMM_SMEM>>>(Xhi, Xlo, Whi, Wlo,
                                                  Qhi, Qlo, Khi, Vthi, Vtlo);

    // attention (single-barrier + rbs prefetch)
    cudaFuncSetAttribute(attn_kernel, cudaFuncAttributeMaxDynamicSharedMemorySize, ATT_SMEM);
    attn_kernel<<<dim3(SEQ / 128, BATCH * NHEADS), 128, ATT_SMEM>>>(
        Qhi, Qlo, Khi, Vthi, Vtlo, Chi, Clo);

    // output projection (R13 config)
    cudaFuncSetAttribute(oproj_kernel, cudaFuncAttributeMaxDynamicSharedMemorySize, HGEMM_SMEM);
    oproj_kernel<<<dim3(DMODEL / 128, NTOK / 128), 128, HGEMM_SMEM>>>(
        Chi, Clo, Whi + 3 * WOFF, Wlo + 3 * WOFF, out);
}

// round 17
// speedup vs baseline: 1.0768x; 1.0768x over previous
#include <cuda_runtime.h>
#include <cuda_fp16.h>
#include <math.h>
#include <stdint.h>

#define BATCH   2
#define SEQ     2048
#define DMODEL  1024
#define NHEADS  16
#define DKV     64
#define INNER   1024
#define NTOK    (BATCH*SEQ)          // 4096
#define RBR     (2*SEQ-1)            // 4095

// -------- scratch (device globals: no allocation allowed) --------
__device__ __half g_Xhi[NTOK*DMODEL],  g_Xlo[NTOK*DMODEL];
__device__ __half g_Whi[4*DMODEL*INNER], g_Wlo[4*DMODEL*INNER];
__device__ __half g_Qhi[NTOK*INNER],  g_Qlo[NTOK*INNER];
__device__ __half g_Khi[NTOK*INNER];
__device__ __half g_Vthi[NTOK*INNER], g_Vtlo[NTOK*INNER];   // transposed [n][token]
__device__ __half g_Chi[NTOK*INNER],  g_Clo[NTOK*INNER];
__device__ float  g_RB[RBR*NHEADS];

// ============================================================
// helpers
// ============================================================
__device__ __forceinline__ uint32_t smem_u32(const void* p) {
    uint32_t a;
    asm("{ .reg .u64 t; cvta.to.shared.u64 t, %1; cvt.u32.u64 %0, t; }" : "=r"(a) : "l"(p));
    return a;
}
__device__ __forceinline__ void cp_async16(uint32_t dst, const void* src) {
    asm volatile("cp.async.cg.shared.global [%0], [%1], 16;\n" :: "r"(dst), "l"(src) : "memory");
}
#define CP_ASYNC_COMMIT() asm volatile("cp.async.commit_group;\n" ::: "memory")
#define CP_ASYNC_WAIT(n)  asm volatile("cp.async.wait_group %0;\n" :: "n"(n) : "memory")

__device__ __forceinline__ void ldmatrix_x4(uint32_t* r, uint32_t addr) {
    asm volatile("ldmatrix.sync.aligned.m8n8.x4.shared.b16 {%0,%1,%2,%3}, [%4];"
                 : "=r"(r[0]), "=r"(r[1]), "=r"(r[2]), "=r"(r[3]) : "r"(addr));
}
__device__ __forceinline__ void mma_f16(float* d, const uint32_t* a, const uint32_t* b) {
    asm volatile(
        "mma.sync.aligned.m16n8k16.row.col.f32.f16.f16.f32 "
        "{%0,%1,%2,%3}, {%4,%5,%6,%7}, {%8,%9}, {%0,%1,%2,%3};"
        : "+f"(d[0]), "+f"(d[1]), "+f"(d[2]), "+f"(d[3])
        : "r"(a[0]), "r"(a[1]), "r"(a[2]), "r"(a[3]), "r"(b[0]), "r"(b[1]));
}
__device__ __forceinline__ void split2(float f0, float f1, uint32_t& hi, uint32_t& lo) {
    __half h0 = __float2half_rn(f0), h1 = __float2half_rn(f1);
    __half l0 = __float2half_rn(f0 - __half2float(h0));
    __half l1 = __float2half_rn(f1 - __half2float(h1));
    hi = (uint32_t)__half_as_ushort(h0) | ((uint32_t)__half_as_ushort(h1) << 16);
    lo = (uint32_t)__half_as_ushort(l0) | ((uint32_t)__half_as_ushort(l1) << 16);
}
__device__ __forceinline__ uint32_t pack_half2(float f0, float f1) {
    __half2 h = __floats2half2_rn(f0, f1);
    return *(uint32_t*)&h;
}

// =============================================================
// Fused pre-processing: one launch.
//  blocks [0, 4096)      : X split (float4 x 256 per block)
//  blocks [4096, 8192)   : weight transpose+split
//  blocks [8192, 8448)   : bias table (256 entries per block)
// Per-element math identical to the three separate kernels.
// =============================================================
#define PRE_SPLIT_BLOCKS 4096
#define PRE_TRANS_BLOCKS 4096
#define PRE_BIAS_BLOCKS  256
#define PRE_TOTAL (PRE_SPLIT_BLOCKS + PRE_TRANS_BLOCKS + PRE_BIAS_BLOCKS)

__global__ __launch_bounds__(256)
void preproc_kernel(const float* __restrict__ X,
                    const float* __restrict__ w0, const float* __restrict__ w1,
                    const float* __restrict__ w2, const float* __restrict__ w3,
                    const float* __restrict__ table,
                    __half* __restrict__ Xhi, __half* __restrict__ Xlo,
                    __half* __restrict__ Whi_base, __half* __restrict__ Wlo_base)
{
    const int blk = blockIdx.x;

    if (blk < PRE_SPLIT_BLOCKS) {
        // ---- X split ----
        int i = blk * 256 + threadIdx.x;     // float4 index, n4 = 1048576 exactly
        float4 v = ((const float4*)X)[i];
        uint32_t h0, l0, h1, l1;
        split2(v.x, v.y, h0, l0);
        split2(v.z, v.w, h1, l1);
        *(uint2*)(Xhi + 4l * i) = make_uint2(h0, h1);
        *(uint2*)(Xlo + 4l * i) = make_uint2(l0, l1);
        return;
    }

    if (blk < PRE_SPLIT_BLOCKS + PRE_TRANS_BLOCKS) {
        // ---- weight transpose + split ----
        __shared__ float tile[32][33];
        int id = blk - PRE_SPLIT_BLOCKS;     // 0..4095
        int z  = id >> 10;                   // weight index 0..3
        int bidx = id & 1023;
        int bxx = bidx & 31, byy = bidx >> 5;

        const float* in = (z == 0) ? w0 : (z == 1) ? w1 : (z == 2) ? w2 : w3;
        __half* hi = Whi_base + (long)z * DMODEL * INNER;
        __half* lo = Wlo_base + (long)z * DMODEL * INNER;

        int tx = threadIdx.x & 31, ty = threadIdx.x >> 5;   // ty 0..7
        int bx = bxx * 32, by = byy * 32;
        int x = bx + tx;
        #pragma unroll
        for (int i = 0; i < 32; i += 8)
            tile[ty + i][tx] = in[(by + ty + i) * DMODEL + x];
        __syncthreads();
        x = by + tx;
        #pragma unroll
        for (int i = 0; i < 32; i += 8) {
            float v = tile[tx][ty + i];
            __half h = __float2half_rn(v);
            __half l = __float2half_rn(v - __half2float(h));
            long idx = (long)(bx + ty + i) * DMODEL + x;
            hi[idx] = h;
            lo[idx] = l;
        }
        return;
    }

    // ---- bias table (256 blocks x 256 entries, fully parallel) ----
    {
        int idx = (blk - PRE_SPLIT_BLOCKS - PRE_TRANS_BLOCKS) * 256 + threadIdx.x;
        if (idx >= RBR * NHEADS) return;
        int rel = idx / NHEADS - (SEQ - 1);
        int h   = idx % NHEADS;
        int bucket = (rel > 0) ? 16 : 0;
        int rp = rel < 0 ? -rel : rel;
        int v;
        if (rp < 8) {
            v = rp;
        } else {
            float f = logf((float)rp * 0.125f) / 2.772588722239781f * 8.0f;
            v = 8 + (int)f;
            if (v > 15) v = 15;
        }
        g_RB[idx] = table[(bucket + v) * NHEADS + h];
    }
}

// =============================================================
// GEMM plumbing (R9/R13 config): 4-stage cp.async ring, per-chunk
// commit, wait(2). 128 thr / 4 warps, warp tile 64x64.
// =============================================================
#define HPAD 24
#define TILE_B 6144
#define STAGE_B 24576
#define NSTAGE 4
#define HGEMM_SMEM (NSTAGE * STAGE_B) // 98304
#define NITER (DMODEL / 16)           // 64

// =============================================================
// Fused QKV projection. Grid (24, 32), 128 threads.
// LPT order: bx 0-7 -> V, 8-15 -> K, 16-23 -> Q. K writes hi only.
// =============================================================
__global__ __launch_bounds__(128)
void qkv_kernel(const __half* __restrict__ Xhi, const __half* __restrict__ Xlo,
                const __half* __restrict__ Whi_base, const __half* __restrict__ Wlo_base,
                __half* __restrict__ Qhi, __half* __restrict__ Qlo,
                __half* __restrict__ Khi,
                __half* __restrict__ Vthi, __half* __restrict__ Vtlo)
{
    extern __shared__ __half hsm[];
    const int mat  = 2 - (blockIdx.x >> 3);   // bx 0-7: V(2), 8-15: K(1), 16-23: Q(0)
    const bool isV = (mat == 2);
    const __half* Bhi = Whi_base + (long)mat * DMODEL * INNER;
    const __half* Blo = Wlo_base + (long)mat * DMODEL * INNER;

    const int tid  = threadIdx.x;
    const int wid  = tid >> 5;
    const int lane = tid & 31;
    const int wr   = wid & 1;
    const int wc   = wid >> 1;
    const long bm  = blockIdx.y * 128;
    const long bn  = (blockIdx.x & 7) * 128;
    const uint32_t s0 = smem_u32(hsm);

    float acc[4][8][4];
    #pragma unroll
    for (int i = 0; i < 4; i++)
        #pragma unroll
        for (int j = 0; j < 8; j++)
            #pragma unroll
            for (int k = 0; k < 4; k++) acc[i][j][k] = 0.0f;

    auto load_tiles = [&](int it, int stage) {
        int k0 = it * 16;
        uint32_t sbase = s0 + stage * STAGE_B;
        #pragma unroll
        for (int i = 0; i < 6; i++) {
            int id  = tid + i * 128;
            int sel = id >> 8;
            int wi  = id & 255;
            int row = wi >> 1, c = wi & 1;
            uint32_t off = sel * TILE_B + row * (HPAD * 2) + c * 16;
            long ao = (bm + row) * (long)DMODEL + k0 + c * 8;
            long bo = (bn + row) * (long)DMODEL + k0 + c * 8;
            const __half* src = (sel == 0) ? Xhi + ao : (sel == 1) ? Xlo + ao : Bhi + bo;
            cp_async16(sbase + off, src);
        }
        if (isV) {
            #pragma unroll
            for (int i = 0; i < 2; i++) {
                int wi  = tid + i * 128;
                int row = wi >> 1, c = wi & 1;
                uint32_t off = 3 * TILE_B + row * (HPAD * 2) + c * 16;
                cp_async16(sbase + off, Blo + (bn + row) * (long)DMODEL + k0 + c * 8);
            }
        }
        CP_ASYNC_COMMIT();
    };

    const int lrow  = lane & 15;
    const int lcolA = (lane >= 16) ? 16 : 0;
    const int brow  = (lane & 7) + ((lane & 16) ? 8 : 0);
    const int bcol  = (lane & 8) ? 16 : 0;

    load_tiles(0, 0);
    load_tiles(1, 1);
    load_tiles(2, 2);

    for (int it = 0; it < NITER; it++) {
        const int buf = it & 3;
        CP_ASYNC_WAIT(2);
        __syncthreads();
        if (it + 3 < NITER) load_tiles(it + 3, (it + 3) & 3);
        else                CP_ASYNC_COMMIT();

        const uint32_t ah  = s0 + buf * STAGE_B;
        const uint32_t al  = ah + TILE_B;
        const uint32_t bhB = ah + 2 * TILE_B;
        const uint32_t blB = ah + 3 * TILE_B;

        uint32_t afh[4][4], afl[4][4];
        #pragma unroll
        for (int mt = 0; mt < 4; mt++) {
            int m = wr * 64 + mt * 16 + lrow;
            ldmatrix_x4(afh[mt], ah + m * (HPAD * 2) + lcolA);
            ldmatrix_x4(afl[mt], al + m * (HPAD * 2) + lcolA);
        }
        uint32_t bfh[4][4], bfl[4][4];
        #pragma unroll
        for (int p = 0; p < 4; p++) {
            int n = wc * 64 + p * 16 + brow;
            ldmatrix_x4(bfh[p], bhB + n * (HPAD * 2) + bcol);
            if (isV) ldmatrix_x4(bfl[p], blB + n * (HPAD * 2) + bcol);
        }
        if (isV) {
            #pragma unroll
            for (int mt = 0; mt < 4; mt++)
                #pragma unroll
                for (int p = 0; p < 4; p++)
                    #pragma unroll
                    for (int sub = 0; sub < 2; sub++) {
                        float* a = acc[mt][2 * p + sub];
                        mma_f16(a, afh[mt], &bfh[p][sub * 2]);
                        mma_f16(a, afh[mt], &bfl[p][sub * 2]);
                        mma_f16(a, afl[mt], &bfh[p][sub * 2]);
                    }
        } else {
            #pragma unroll
            for (int mt = 0; mt < 4; mt++)
                #pragma unroll
                for (int p = 0; p < 4; p++)
                    #pragma unroll
                    for (int sub = 0; sub < 2; sub++) {
                        float* a = acc[mt][2 * p + sub];
                        mma_f16(a, afh[mt], &bfh[p][sub * 2]);
                        mma_f16(a, afl[mt], &bfh[p][sub * 2]);
                    }
        }
    }

    // epilogue
    __half* Chi = (mat == 0) ? Qhi : (mat == 1) ? Khi : Vthi;
    __half* Clo = (mat == 0) ? Qlo : Vtlo;      // only used for Q and V
    #pragma unroll
    for (int mt = 0; mt < 4; mt++) {
        long m0 = bm + wr * 64 + mt * 16 + (lane >> 2);
        #pragma unroll
        for (int nt = 0; nt < 8; nt++) {
            long n0 = bn + wc * 64 + nt * 8 + (lane & 3) * 2;
            float* a = acc[mt][nt];
            if (!isV) {
                uint32_t h, l;
                split2(a[0], a[1], h, l);
                *(uint32_t*)(Chi + m0 * INNER + n0) = h;
                if (mat == 0) *(uint32_t*)(Clo + m0 * INNER + n0) = l;
                split2(a[2], a[3], h, l);
                *(uint32_t*)(Chi + (m0 + 8) * INNER + n0) = h;
                if (mat == 0) *(uint32_t*)(Clo + (m0 + 8) * INNER + n0) = l;
            } else {
                #pragma unroll
                for (int e = 0; e < 4; e++) {
                    long m = m0 + ((e >= 2) ? 8 : 0);
                    long n = n0 + (e & 1);
                    __half h = __float2half_rn(a[e]);
                    __half l = __float2half_rn(a[e] - __half2float(h));
                    Chi[n * NTOK + m] = h;
                    Clo[n * NTOK + m] = l;
                }
            }
        }
    }
}

// =============================================================
// O-projection GEMM (3-MMA, float out) — R9/R13 config.
// =============================================================
__global__ __launch_bounds__(128)
void oproj_kernel(const __half* __restrict__ Ahi, const __half* __restrict__ Alo,
                  const __half* __restrict__ Bhi, const __half* __restrict__ Blo,
                  float* __restrict__ Cf)
{
    extern __shared__ __half hsm[];
    const int tid  = threadIdx.x;
    const int wid  = tid >> 5;
    const int lane = tid & 31;
    const int wr   = wid & 1;
    const int wc   = wid >> 1;
    const long bm  = blockIdx.y * 128;
    const long bn  = blockIdx.x * 128;
    const uint32_t s0 = smem_u32(hsm);

    float acc[4][8][4];
    #pragma unroll
    for (int i = 0; i < 4; i++)
        #pragma unroll
        for (int j = 0; j < 8; j++)
            #pragma unroll
            for (int k = 0; k < 4; k++) acc[i][j][k] = 0.0f;

    auto load_tiles = [&](int it, int stage) {
        int k0 = it * 16;
        uint32_t sbase = s0 + stage * STAGE_B;
        #pragma unroll
        for (int i = 0; i < 8; i++) {
            int id  = tid + i * 128;          // 0..1023
            int sel = id >> 8;                // 0 Ahi, 1 Alo, 2 Bhi, 3 Blo
            int wi  = id & 255;
            int row = wi >> 1, c = wi & 1;
            uint32_t off = sel * TILE_B + row * (HPAD * 2) + c * 16;
            long ao = (bm + row) * (long)DMODEL + k0 + c * 8;
            long bo = (bn + row) * (long)DMODEL + k0 + c * 8;
            const __half* src = (sel == 0) ? Ahi + ao : (sel == 1) ? Alo + ao
                              : (sel == 2) ? Bhi + bo : Blo + bo;
            cp_async16(sbase + off, src);
        }
        CP_ASYNC_COMMIT();
    };

    const int lrow  = lane & 15;
    const int lcolA = (lane >= 16) ? 16 : 0;
    const int brow  = (lane & 7) + ((lane & 16) ? 8 : 0);
    const int bcol  = (lane & 8) ? 16 : 0;

    load_tiles(0, 0);
    load_tiles(1, 1);
    load_tiles(2, 2);

    for (int it = 0; it < NITER; it++) {
        const int buf = it & 3;
        CP_ASYNC_WAIT(2);
        __syncthreads();
        if (it + 3 < NITER) load_tiles(it + 3, (it + 3) & 3);
        else                CP_ASYNC_COMMIT();

        const uint32_t ah  = s0 + buf * STAGE_B;
        const uint32_t al  = ah + TILE_B;
        const uint32_t bhB = ah + 2 * TILE_B;
        const uint32_t blB = ah + 3 * TILE_B;

        uint32_t afh[4][4], afl[4][4];
        #pragma unroll
        for (int mt = 0; mt < 4; mt++) {
            int m = wr * 64 + mt * 16 + lrow;
            ldmatrix_x4(afh[mt], ah + m * (HPAD * 2) + lcolA);
            ldmatrix_x4(afl[mt], al + m * (HPAD * 2) + lcolA);
        }
        uint32_t bfh[4][4], bfl[4][4];
        #pragma unroll
        for (int p = 0; p < 4; p++) {
            int n = wc * 64 + p * 16 + brow;
            ldmatrix_x4(bfh[p], bhB + n * (HPAD * 2) + bcol);
            ldmatrix_x4(bfl[p], blB + n * (HPAD * 2) + bcol);
        }
        #pragma unroll
        for (int mt = 0; mt < 4; mt++)
            #pragma unroll
            for (int p = 0; p < 4; p++)
                #pragma unroll
                for (int sub = 0; sub < 2; sub++) {
                    float* a = acc[mt][2 * p + sub];
                    mma_f16(a, afh[mt], &bfh[p][sub * 2]);
                    mma_f16(a, afh[mt], &bfl[p][sub * 2]);
                    mma_f16(a, afl[mt], &bfh[p][sub * 2]);
                }
    }

    #pragma unroll
    for (int mt = 0; mt < 4; mt++) {
        long m0 = bm + wr * 64 + mt * 16 + (lane >> 2);
        #pragma unroll
        for (int nt = 0; nt < 8; nt++) {
            long n0 = bn + wc * 64 + nt * 8 + (lane & 3) * 2;
            float* a = acc[mt][nt];
            *(float2*)(Cf + m0 * INNER + n0)       = make_float2(a[0], a[1]);
            *(float2*)(Cf + (m0 + 8) * INNER + n0) = make_float2(a[2], a[3]);
        }
    }
}

// =============================================================
// fp16-split flash attention: single barrier per k-tile, bias
// slice double-buffered and prefetched one tile ahead.
// =============================================================
#define KSTAGE 27648
#define QOFF   27648
#define RBOFF  (QOFF + 36864)
#define ATT_SMEM (RBOFF + 2*192*4)
#define KROWB 144

__global__ __launch_bounds__(128, 2)
void attn_kernel(const __half* __restrict__ Qhi, const __half* __restrict__ Qlo,
                 const __half* __restrict__ Khi,
                 const __half* __restrict__ Vthi, const __half* __restrict__ Vtlo,
                 __half* __restrict__ Chi, __half* __restrict__ Clo)
{
    extern __shared__ char smraw[];
    float* rbs = (float*)(smraw + RBOFF);   // two buffers of 192 floats
    const int tid  = threadIdx.x;
    const int w    = tid >> 5;
    const int lane = tid & 31;
    const int bh   = blockIdx.y;
    const int b    = bh >> 4;
    const int h    = bh & 15;
    const int q0   = blockIdx.x * 128;
    const uint32_t sb = smem_u32(smraw);
    const int grow = lane >> 2;
    const int gc   = (lane & 3) * 2;

    auto load_kv = [&](int t, int stage) {
        int k0 = t * 64;
        uint32_t sbase = sb + stage * KSTAGE;
        #pragma unroll
        for (int i = 0; i < 12; i++) {
            int id  = tid + i * 128;
            int sel = id >> 9;
            int wi  = id & 511;
            int row = wi >> 3, c = wi & 7;
            uint32_t dst = sbase + sel * 9216 + row * KROWB + c * 16;
            const __half* src;
            if (sel == 0) {
                src = Khi + (long)(b * SEQ + k0 + row) * INNER + h * DKV + c * 8;
            } else {
                const __half* base = (sel == 2) ? Vtlo : Vthi;
                src = base + (long)(h * DKV + row) * NTOK + b * SEQ + k0 + c * 8;
            }
            cp_async16(dst, src);
        }
        CP_ASYNC_COMMIT();
    };
    auto load_rbs = [&](int t) {
        float* dst = rbs + (t & 1) * 192;
        for (int i = tid; i < 191; i += 128)
            dst[i] = g_RB[(t * 64 - q0 + i - 127 + SEQ - 1) * NHEADS + h];
    };

    // ---- prologue: Q + kv0, rbs buffer 0 ----
    #pragma unroll
    for (int i = 0; i < 16; i++) {
        int id  = tid + i * 128;
        int sel = id >> 10;
        int wi  = id & 1023;
        int row = wi >> 3, c = wi & 7;
        uint32_t dst = sb + QOFF + sel * 18432 + row * KROWB + c * 16;
        const __half* src = (sel ? Qlo : Qhi) +
                            (long)(b * SEQ + q0 + row) * INNER + h * DKV + c * 8;
        cp_async16(dst, src);
    }
    load_kv(0, 0);
    load_rbs(0);
    CP_ASYNC_WAIT(0);
    __syncthreads();

    uint32_t qh[2][4][4], ql[2][4][4];
    {
        uint32_t qbh = sb + QOFF;
        uint32_t qbl = qbh + 18432;
        int cofs = (lane >= 16) ? 16 : 0;
        #pragma unroll
        for (int hf = 0; hf < 2; hf++) {
            int r = w * 32 + hf * 16 + (lane & 15);
            #pragma unroll
            for (int ks = 0; ks < 4; ks++) {
                ldmatrix_x4(qh[hf][ks], qbh + r * KROWB + ks * 32 + cofs);
                ldmatrix_x4(ql[hf][ks], qbl + r * KROWB + ks * 32 + cofs);
            }
        }
    }

    float m[2][2], l[2][2];
    float o[2][8][4];
    #pragma unroll
    for (int hf = 0; hf < 2; hf++) {
        m[hf][0] = m[hf][1] = -3.0e38f;
        l[hf][0] = l[hf][1] = 0.0f;
        #pragma unroll
        for (int nt = 0; nt < 8; nt++)
            #pragma unroll
            for (int e = 0; e < 4; e++) o[hf][nt][e] = 0.0f;
    }

    for (int t = 0; t < SEQ / 64; t++) {
        __syncthreads();   // one barrier per tile
        if (t + 1 < SEQ / 64) {
            load_kv(t + 1, (t + 1) & 1);
            load_rbs(t + 1);            // prefetch bias for next tile
            CP_ASYNC_WAIT(1);           // kv_t complete
        } else {
            CP_ASYNC_WAIT(0);
        }

        const char* kp = smraw + (t & 1) * KSTAGE;
        const char* vh = kp + 9216;
        const char* vl = kp + 18432;
        const float* rb = rbs + (t & 1) * 192;

        float s[2][8][4];
        #pragma unroll
        for (int hf = 0; hf < 2; hf++)
            #pragma unroll
            for (int nt = 0; nt < 8; nt++)
                #pragma unroll
                for (int e = 0; e < 4; e++) s[hf][nt][e] = 0.0f;

        #pragma unroll
        for (int ks = 0; ks < 4; ks++) {
            #pragma unroll
            for (int nt = 0; nt < 8; nt++) {
                uint32_t off = (nt * 8 + grow) * KROWB + ks * 32 + gc * 2;
                uint32_t bh_[2];
                bh_[0] = *(const uint32_t*)(kp + off);
                bh_[1] = *(const uint32_t*)(kp + off + 16);
                mma_f16(s[0][nt], qh[0][ks], bh_);
                mma_f16(s[0][nt], ql[0][ks], bh_);
                mma_f16(s[1][nt], qh[1][ks], bh_);
                mma_f16(s[1][nt], ql[1][ks], bh_);
            }
        }

        #pragma unroll
        for (int hf = 0; hf < 2; hf++) {
            const int rb0 = 127 - (w * 32 + hf * 16 + grow);
            #pragma unroll
            for (int nt = 0; nt < 8; nt++) {
                int cb = nt * 8 + gc;
                s[hf][nt][0] += rb[cb + rb0];
                s[hf][nt][1] += rb[cb + 1 + rb0];
                s[hf][nt][2] += rb[cb + rb0 - 8];
                s[hf][nt][3] += rb[cb + 1 + rb0 - 8];
            }
            float tm0 = -3.0e38f, tm1 = -3.0e38f;
            #pragma unroll
            for (int nt = 0; nt < 8; nt++) {
                tm0 = fmaxf(tm0, fmaxf(s[hf][nt][0], s[hf][nt][1]));
                tm1 = fmaxf(tm1, fmaxf(s[hf][nt][2], s[hf][nt][3]));
            }
            tm0 = fmaxf(tm0, __shfl_xor_sync(0xffffffffu, tm0, 1));
            tm0 = fmaxf(tm0, __shfl_xor_sync(0xffffffffu, tm0, 2));
            tm1 = fmaxf(tm1, __shfl_xor_sync(0xffffffffu, tm1, 1));
            tm1 = fmaxf(tm1, __shfl_xor_sync(0xffffffffu, tm1, 2));
            float nm0 = fmaxf(m[hf][0], tm0), nm1 = fmaxf(m[hf][1], tm1);
            float sc0 = __expf(m[hf][0] - nm0), sc1 = __expf(m[hf][1] - nm1);
            float ls0 = 0.0f, ls1 = 0.0f;
            #pragma unroll
            for (int nt = 0; nt < 8; nt++) {
                s[hf][nt][0] = __expf(s[hf][nt][0] - nm0); ls0 += s[hf][nt][0];
                s[hf][nt][1] = __expf(s[hf][nt][1] - nm0); ls0 += s[hf][nt][1];
                s[hf][nt][2] = __expf(s[hf][nt][2] - nm1); ls1 += s[hf][nt][2];
                s[hf][nt][3] = __expf(s[hf][nt][3] - nm1); ls1 += s[hf][nt][3];
            }
            ls0 += __shfl_xor_sync(0xffffffffu, ls0, 1);
            ls0 += __shfl_xor_sync(0xffffffffu, ls0, 2);
            ls1 += __shfl_xor_sync(0xffffffffu, ls1, 1);
            ls1 += __shfl_xor_sync(0xffffffffu, ls1, 2);
            l[hf][0] = l[hf][0] * sc0 + ls0;
            l[hf][1] = l[hf][1] * sc1 + ls1;
            m[hf][0] = nm0;  m[hf][1] = nm1;
            #pragma unroll
            for (int nt = 0; nt < 8; nt++) {
                o[hf][nt][0] *= sc0; o[hf][nt][1] *= sc0;
                o[hf][nt][2] *= sc1; o[hf][nt][3] *= sc1;
            }
        }

        #pragma unroll
        for (int ks = 0; ks < 4; ks++) {
            uint32_t ph[2][4];
            #pragma unroll
            for (int hf = 0; hf < 2; hf++) {
                ph[hf][0] = pack_half2(s[hf][2*ks][0],   s[hf][2*ks][1]);
                ph[hf][1] = pack_half2(s[hf][2*ks][2],   s[hf][2*ks][3]);
                ph[hf][2] = pack_half2(s[hf][2*ks+1][0], s[hf][2*ks+1][1]);
                ph[hf][3] = pack_half2(s[hf][2*ks+1][2], s[hf][2*ks+1][3]);
            }
            #pragma unroll
            for (int nt = 0; nt < 8; nt++) {
                uint32_t off = (nt * 8 + grow) * KROWB + ks * 32 + gc * 2;
                uint32_t vh_[2], vl_[2];
                vh_[0] = *(const uint32_t*)(vh + off);
                vh_[1] = *(const uint32_t*)(vh + off + 16);
                vl_[0] = *(const uint32_t*)(vl + off);
                vl_[1] = *(const uint32_t*)(vl + off + 16);
                mma_f16(o[0][nt], ph[0], vh_);
                mma_f16(o[0][nt], ph[0], vl_);
                mma_f16(o[1][nt], ph[1], vh_);
                mma_f16(o[1][nt], ph[1], vl_);
            }
        }
    }

    #pragma unroll
    for (int hf = 0; hf < 2; hf++) {
        float i0 = 1.0f / l[hf][0], i1 = 1.0f / l[hf][1];
        long tok0 = (long)b * SEQ + q0 + w * 32 + hf * 16 + grow;
        #pragma unroll
        for (int nt = 0; nt < 8; nt++) {
            long col = h * DKV + nt * 8 + gc;
            uint32_t hh, ll;
            split2(o[hf][nt][0] * i0, o[hf][nt][1] * i0, hh, ll);
            *(uint32_t*)(Chi + tok0 * INNER + col) = hh;
            *(uint32_t*)(Clo + tok0 * INNER + col) = ll;
            split2(o[hf][nt][2] * i1, o[hf][nt][3] * i1, hh, ll);
            *(uint32_t*)(Chi + (tok0 + 8) * INNER + col) = hh;
            *(uint32_t*)(Clo + (tok0 + 8) * INNER + col) = ll;
        }
    }
}

// =============================================================
// Host launcher
// =============================================================
extern "C" void kernel_launch(void* const* d_in, const int* in_sizes, int n_in,
                              void* d_out, int out_size)
{
    const float* X   = (const float*)d_in[0];
    const float* wq  = (const float*)d_in[1];
    const float* wk  = (const float*)d_in[2];
    const float* wv  = (const float*)d_in[3];
    const float* wo  = (const float*)d_in[4];
    const float* rbt = (const float*)d_in[5];
    float* out = (float*)d_out;

    __half *Xhi, *Xlo, *Whi, *Wlo, *Qhi, *Qlo, *Khi, *Vthi, *Vtlo, *Chi, *Clo;
    cudaGetSymbolAddress((void**)&Xhi,  g_Xhi);   cudaGetSymbolAddress((void**)&Xlo,  g_Xlo);
    cudaGetSymbolAddress((void**)&Whi,  g_Whi);   cudaGetSymbolAddress((void**)&Wlo,  g_Wlo);
    cudaGetSymbolAddress((void**)&Qhi,  g_Qhi);   cudaGetSymbolAddress((void**)&Qlo,  g_Qlo);
    cudaGetSymbolAddress((void**)&Khi,  g_Khi);
    cudaGetSymbolAddress((void**)&Vthi, g_Vthi);  cudaGetSymbolAddress((void**)&Vtlo, g_Vtlo);
    cudaGetSymbolAddress((void**)&Chi,  g_Chi);   cudaGetSymbolAddress((void**)&Clo,  g_Clo);

    const long WOFF = (long)DMODEL * INNER;

    // fused preprocessing (one launch, fully parallel bias table)
    preproc_kernel<<<PRE_TOTAL, 256>>>(X, wq, wk, wv, wo, rbt, Xhi, Xlo, Whi, Wlo);

    // fused QKV projections (R13 config: R9-shape loop, LPT order, K hi-only)
    cudaFuncSetAttribute(qkv_kernel, cudaFuncAttributeMaxDynamicSharedMemorySize, HGEMM_SMEM);
    qkv_kernel<<<dim3(24, 32), 128, HGEMM_SMEM>>>(Xhi, Xlo, Whi, Wlo,
                                                  Qhi, Qlo, Khi, Vthi, Vtlo);

    // attention (single-barrier + rbs prefetch)
    cudaFuncSetAttribute(attn_kernel, cudaFuncAttributeMaxDynamicSharedMemorySize, ATT_SMEM);
    attn_kernel<<<dim3(SEQ / 128, BATCH * NHEADS), 128, ATT_SMEM>>>(
        Qhi, Qlo, Khi, Vthi, Vtlo, Chi, Clo);

    // output projection (R13 config)
    cudaFuncSetAttribute(oproj_kernel, cudaFuncAttributeMaxDynamicSharedMemorySize, HGEMM_SMEM);
    oproj_kernel<<<dim3(DMODEL / 128, NTOK / 128), 128, HGEMM_SMEM>>>(
        Chi, Clo, Whi + 3 * WOFF, Wlo + 3 * WOFF, out);
}